// round 13
// baseline (speedup 1.0000x reference)
#include <cuda_runtime.h>
#include <cuda_bf16.h>
#include <cstdint>

#define NROWS 16384
#define SEG   ((size_t)NROWS * 64)

// split bf16 buffers
static __device__ __nv_bfloat16 g_XH  [2048 * 1024];
static __device__ __nv_bfloat16 g_XL  [2048 * 1024];
static __device__ __nv_bfloat16 g_WaH [1024 * 1536];   // [Wq | Wkv] packed
static __device__ __nv_bfloat16 g_WaL [1024 * 1536];
static __device__ __nv_bfloat16 g_WoH [512 * 1024];
static __device__ __nv_bfloat16 g_WoL [512 * 1024];
static __device__ __nv_bfloat16 g_QKVH[3 * NROWS * 64];  // Q | K | V
static __device__ __nv_bfloat16 g_QKVL[3 * NROWS * 64];
static __device__ __nv_bfloat16 g_AoH [NROWS * 64];
static __device__ __nv_bfloat16 g_AoL [NROWS * 64];

// ---------------------------- helpers --------------------------------------
__device__ __forceinline__ uint32_t smem_u32(const void* p) {
    uint32_t a;
    asm("{ .reg .u64 t; cvta.to.shared.u64 t, %1; cvt.u32.u64 %0, t; }" : "=r"(a) : "l"(p));
    return a;
}
__device__ __forceinline__ uint32_t swz(uint32_t b) { return b ^ ((b >> 3) & 0x70); }

__device__ __forceinline__ void cpa16(uint32_t dst, const void* src) {
    asm volatile("cp.async.cg.shared.global [%0], [%1], 16;" :: "r"(dst), "l"(src) : "memory");
}
#define CP_COMMIT() asm volatile("cp.async.commit_group;" ::: "memory")
#define CP_WAIT0()  asm volatile("cp.async.wait_group 0;" ::: "memory")

__device__ __forceinline__ void ldsm4(uint32_t* r, uint32_t addr) {
    asm volatile("ldmatrix.sync.aligned.m8n8.x4.shared.b16 {%0,%1,%2,%3}, [%4];"
        : "=r"(r[0]), "=r"(r[1]), "=r"(r[2]), "=r"(r[3]) : "r"(addr));
}
__device__ __forceinline__ void ldsm4t(uint32_t* r, uint32_t addr) {
    asm volatile("ldmatrix.sync.aligned.m8n8.x4.trans.shared.b16 {%0,%1,%2,%3}, [%4];"
        : "=r"(r[0]), "=r"(r[1]), "=r"(r[2]), "=r"(r[3]) : "r"(addr));
}
__device__ __forceinline__ void mma16816(float* c, const uint32_t* a, const uint32_t* b) {
    asm volatile("mma.sync.aligned.m16n8k16.row.col.f32.bf16.bf16.f32 "
        "{%0,%1,%2,%3}, {%4,%5,%6,%7}, {%8,%9}, {%0,%1,%2,%3};"
        : "+f"(c[0]), "+f"(c[1]), "+f"(c[2]), "+f"(c[3])
        : "r"(a[0]), "r"(a[1]), "r"(a[2]), "r"(a[3]), "r"(b[0]), "r"(b[1]));
}
__device__ __forceinline__ uint32_t pack_bf16x2(float a, float b) {
    uint32_t h; asm("cvt.rn.bf16x2.f32 %0, %1, %2;" : "=r"(h) : "f"(b), "f"(a));
    return h;   // lo halfword = a, hi halfword = b
}
__device__ __forceinline__ void split_store(__nv_bfloat16* H, __nv_bfloat16* L,
                                            size_t off, float a, float b) {
    uint32_t h = pack_bf16x2(a, b);
    float ha = __int_as_float(h << 16);
    float hb = __int_as_float(h & 0xffff0000u);
    uint32_t l = pack_bf16x2(a - ha, b - hb);
    *(uint32_t*)(H + off) = h;
    *(uint32_t*)(L + off) = l;
}
// exp(0.125*s) via exp2 poly; |s| < ~24 here.
__device__ __forceinline__ float fexp8(float s) {
    float x = s * 0.18033688f;                 // 0.125 * log2(e)
    float t = x + 12582912.0f;
    int  ni = __float_as_int(t) - 0x4B400000;
    float r = x - (t - 12582912.0f);
    float p = 1.3333558e-3f;
    p = fmaf(p, r, 9.6181291e-3f);
    p = fmaf(p, r, 5.5504109e-2f);
    p = fmaf(p, r, 2.4022651e-1f);
    p = fmaf(p, r, 6.9314718e-1f);
    p = fmaf(p, r, 1.0f);
    return p * __int_as_float((ni + 127) << 23);
}

// ------------------------------- prep --------------------------------------
__global__ void prep_split(const float* __restrict__ X, __nv_bfloat16* __restrict__ H,
                           __nv_bfloat16* __restrict__ L)
{
    int i = blockIdx.x * 256 + threadIdx.x;
    float v = X[i];
    __nv_bfloat16 h = __float2bfloat16(v);
    H[i] = h;
    L[i] = __float2bfloat16(v - __bfloat162float(h));
}

__global__ void prep_pack(const float* __restrict__ Wq, const float* __restrict__ Wkv,
                          __nv_bfloat16* __restrict__ H, __nv_bfloat16* __restrict__ L)
{
    int i = blockIdx.x * 256 + threadIdx.x;     // over 1024*1536
    int k = i / 1536, c = i - k * 1536;
    float v = (c < 512) ? Wq[k * 512 + c] : Wkv[k * 1024 + (c - 512)];
    __nv_bfloat16 h = __float2bfloat16(v);
    H[i] = h;
    L[i] = __float2bfloat16(v - __bfloat162float(h));
}

// ---------------------------------------------------------------------------
// Split-bf16 HMMA GEMM.  C[M,N] = A[M,K] @ B[K,N] (3-term hi/lo).
// CTA = 128x128 C tile, 8 warps (m16 x n128), K chunks of 64, 2-buffer cp.async.
// mode 0: fp32 C (+bias).  mode 1: split-bf16 store with 512-col segment
// routing: off = (col>>9)*seg + row*ldcs + (col&511).
// ---------------------------------------------------------------------------
__global__ __launch_bounds__(256, 1)
void hgemm(const __nv_bfloat16* __restrict__ AH, const __nv_bfloat16* __restrict__ AL, int lda,
           const __nv_bfloat16* __restrict__ BH, const __nv_bfloat16* __restrict__ BL, int ldb,
           int Kdim,
           float* __restrict__ Cf, const float* __restrict__ bias, int ldc,
           __nv_bfloat16* __restrict__ CH, __nv_bfloat16* __restrict__ CL, int ldcs,
           size_t seg, int mode)
{
    extern __shared__ char smem[];
    const int tid = threadIdx.x, w = tid >> 5, lane = tid & 31;
    const int g = lane & 3, hr = lane >> 2;
    const uint32_t smb = smem_u32(smem);
    const int n0 = blockIdx.x * 128, m0 = blockIdx.y * 128;
    const int S = Kdim >> 6;

    auto load_stage = [&](int s, int b) {
        const uint32_t bb = smb + (uint32_t)b * 65536;
        const int k0 = s << 6;
        #pragma unroll
        for (int j = 0; j < 4; j++) {
            int f = tid + 256 * j;
            {   // A: 128 rows x 8 chunks
                int row = f >> 3, c = f & 7;
                uint32_t d = swz((uint32_t)(row * 128 + c * 16));
                const size_t so = (size_t)(m0 + row) * lda + k0 + c * 8;
                cpa16(bb + d,         AH + so);
                cpa16(bb + 16384 + d, AL + so);
            }
            {   // B: 64 k-rows x 16 chunks -> 2 panels
                int k = f >> 4, t = f & 15;
                uint32_t d = (uint32_t)((t >> 3) * 8192) + swz((uint32_t)(k * 128 + (t & 7) * 16));
                const size_t so = (size_t)(k0 + k) * ldb + n0 + t * 8;
                cpa16(bb + 32768 + d, BH + so);
                cpa16(bb + 49152 + d, BL + so);
            }
        }
        CP_COMMIT();
    };

    load_stage(0, 0);
    CP_WAIT0();
    __syncthreads();

    float acc[16][4];
    #pragma unroll
    for (int j = 0; j < 16; j++)
        #pragma unroll
        for (int e = 0; e < 4; e++) acc[j][e] = 0.f;

    const int arow = w * 16 + ((lane >> 3) & 1) * 8 + (lane & 7);
    const int acolh = ((lane >> 4) & 1) * 8;
    const int brow8 = ((lane >> 3) & 1) * 8 + (lane & 7);
    const int bcolh = ((lane >> 4) & 1) * 8;

    for (int i = 0; i < S; i++) {
        const uint32_t cb = smb + (uint32_t)(i & 1) * 65536;
        if (i + 1 < S) load_stage(i + 1, (i + 1) & 1);

        #pragma unroll
        for (int kk = 0; kk < 4; kk++) {
            uint32_t ah[4], al[4];
            uint32_t sa = swz((uint32_t)(arow * 128 + (kk * 16 + acolh) * 2));
            ldsm4(ah, cb + sa);
            ldsm4(al, cb + 16384 + sa);
            #pragma unroll
            for (int t = 0; t < 8; t++) {
                int ncol = ((t * 16) & 63) + bcolh;
                uint32_t sb = (uint32_t)((t >> 2) * 8192)
                            + swz((uint32_t)((kk * 16 + brow8) * 128 + ncol * 2));
                uint32_t bh[4], bl[4];
                ldsm4t(bh, cb + 32768 + sb);
                ldsm4t(bl, cb + 49152 + sb);
                mma16816(acc[2 * t],     ah, bh);
                mma16816(acc[2 * t],     ah, bl);
                mma16816(acc[2 * t],     al, bh);
                mma16816(acc[2 * t + 1], ah, bh + 2);
                mma16816(acc[2 * t + 1], ah, bl + 2);
                mma16816(acc[2 * t + 1], al, bh + 2);
            }
        }
        if (i + 1 < S) CP_WAIT0();
        __syncthreads();
    }

    const int r0 = m0 + w * 16 + hr;
    const int r1 = r0 + 8;
    if (mode == 0) {
        #pragma unroll
        for (int jo = 0; jo < 16; jo++) {
            int col = n0 + (jo >> 1) * 16 + (jo & 1) * 8 + 2 * g;
            float bx = bias ? bias[col] : 0.f, by = bias ? bias[col + 1] : 0.f;
            *(float2*)(Cf + (size_t)r0 * ldc + col) = make_float2(acc[jo][0] + bx, acc[jo][1] + by);
            *(float2*)(Cf + (size_t)r1 * ldc + col) = make_float2(acc[jo][2] + bx, acc[jo][3] + by);
        }
    } else {
        #pragma unroll
        for (int jo = 0; jo < 16; jo++) {
            int col = n0 + (jo >> 1) * 16 + (jo & 1) * 8 + 2 * g;
            size_t base = (size_t)(col >> 9) * seg + (size_t)(col & 511);
            split_store(CH, CL, base + (size_t)r0 * ldcs, acc[jo][0], acc[jo][1]);
            split_store(CH, CL, base + (size_t)r1 * ldcs, acc[jo][2], acc[jo][3]);
        }
    }
}

// ---------------------------------------------------------------------------
// HMMA flash attention, split-bf16 3-term, no online max.
// CTA = 128 q rows; warps tiled m32 x n64 (mi = w&3, nh = w>>2) so each warp
// reads only HALF of the K and V tiles -> SMEM crossbar traffic halved.
// Partner warps (same mi, nh=0/1) reduce partial O / rowsum once at the end.
// SMEM: Qhi 16K | Qlo 16K | 2 x { KH 16K | KL 16K | VH 16K | VL 16K }.
// ---------------------------------------------------------------------------
__global__ __launch_bounds__(256, 1)
void flashmma(const __nv_bfloat16* __restrict__ QH, const __nv_bfloat16* __restrict__ QL,
              const __nv_bfloat16* __restrict__ KH, const __nv_bfloat16* __restrict__ KL,
              const __nv_bfloat16* __restrict__ VH, const __nv_bfloat16* __restrict__ VL,
              __nv_bfloat16* __restrict__ OH, __nv_bfloat16* __restrict__ OL)
{
    extern __shared__ char smem[];
    const int tid = threadIdx.x, w = tid >> 5, lane = tid & 31;
    const int g = lane & 3, hr = lane >> 2;
    const int mi = w & 3, nh = w >> 2;
    const uint32_t smb = smem_u32(smem);
    const uint32_t QHs = smb, QLs = smb + 16384;
    const uint32_t BUF = smb + 32768;          // 2 x 64KB
    const int q0 = blockIdx.x * 128;

    // prologue: K/V tile 0 + Q tile via cp.async
    #pragma unroll
    for (int j = 0; j < 4; j++) {
        int f = tid + 256 * j;
        uint32_t d = swz((uint32_t)f * 16);
        cpa16(BUF +         d, KH + (size_t)f * 8);
        cpa16(BUF + 16384 + d, KL + (size_t)f * 8);
        cpa16(BUF + 32768 + d, VH + (size_t)f * 8);
        cpa16(BUF + 49152 + d, VL + (size_t)f * 8);
        int row = f >> 3, c = f & 7;
        uint32_t dq = swz((uint32_t)(row * 128 + c * 16));
        const size_t so = (size_t)(q0 + row) * 64 + c * 8;
        cpa16(QHs + dq, QH + so);
        cpa16(QLs + dq, QL + so);
    }
    CP_COMMIT();
    CP_WAIT0();
    __syncthreads();

    // persistent Q A-fragments: m32 (two m16 row blocks) x k64
    uint32_t qh[4][2][4], ql[4][2][4];
    #pragma unroll
    for (int ks = 0; ks < 4; ks++)
        #pragma unroll
        for (int r = 0; r < 2; r++) {
            int row = mi * 32 + r * 16 + ((lane >> 3) & 1) * 8 + (lane & 7);
            int col = ks * 16 + ((lane >> 4) & 1) * 8;
            uint32_t sb = swz((uint32_t)(row * 128 + col * 2));
            ldsm4(qh[ks][r], QHs + sb);
            ldsm4(ql[ks][r], QLs + sb);
        }

    float oc[2][8][4];
    #pragma unroll
    for (int r = 0; r < 2; r++)
        #pragma unroll
        for (int j = 0; j < 8; j++)
            #pragma unroll
            for (int e = 0; e < 4; e++) oc[r][j][e] = 0.f;
    float lsum[2][2] = {};

    for (int i = 0; i < 128; i++) {
        const uint32_t cb = BUF + (uint32_t)(i & 1) * 65536;

        if (i < 127) {
            size_t base = (size_t)(i + 1) * 8192;
            uint32_t nb = BUF + (uint32_t)((i + 1) & 1) * 65536;
            #pragma unroll
            for (int j = 0; j < 4; j++) {
                int f = tid + 256 * j;
                uint32_t d = swz((uint32_t)f * 16);
                cpa16(nb +         d, KH + base + (size_t)f * 8);
                cpa16(nb + 16384 + d, KL + base + (size_t)f * 8);
                cpa16(nb + 32768 + d, VH + base + (size_t)f * 8);
                cpa16(nb + 49152 + d, VL + base + (size_t)f * 8);
            }
            CP_COMMIT();
        }

        // ---- S = Q K^T over this warp's key-half (m32 x n64) ----
        float sc[16][4];
        #pragma unroll
        for (int j = 0; j < 16; j++)
            #pragma unroll
            for (int e = 0; e < 4; e++) sc[j][e] = 0.f;

        #pragma unroll
        for (int ks = 0; ks < 4; ks++) {
            #pragma unroll
            for (int np = 0; np < 4; np++) {
                int krow = nh * 64 + np * 16 + ((lane >> 4) & 1) * 8 + (lane & 7);
                int kcol = ks * 16 + ((lane >> 3) & 1) * 8;
                uint32_t sb = swz((uint32_t)(krow * 128 + kcol * 2));
                uint32_t bh[4], bl[4];
                ldsm4(bh, cb + sb);
                ldsm4(bl, cb + 16384 + sb);
                #pragma unroll
                for (int r = 0; r < 2; r++) {
                    float* s0 = sc[r * 8 + np * 2];
                    float* s1 = sc[r * 8 + np * 2 + 1];
                    mma16816(s0, qh[ks][r], bh);
                    mma16816(s0, qh[ks][r], bl);
                    mma16816(s0, ql[ks][r], bh);
                    mma16816(s1, qh[ks][r], bh + 2);
                    mma16816(s1, qh[ks][r], bl + 2);
                    mma16816(s1, ql[ks][r], bh + 2);
                }
            }
        }

        // ---- p = exp(s/8); per-(row-block, frag-half) partial sums ----
        #pragma unroll
        for (int j = 0; j < 16; j++) {
            int r = j >> 3;
            sc[j][0] = fexp8(sc[j][0]); sc[j][1] = fexp8(sc[j][1]);
            sc[j][2] = fexp8(sc[j][2]); sc[j][3] = fexp8(sc[j][3]);
            lsum[r][0] += sc[j][0] + sc[j][1];
            lsum[r][1] += sc[j][2] + sc[j][3];
        }

        // ---- O_partial += P V over this warp's k-half ----
        #pragma unroll
        for (int kp = 0; kp < 4; kp++) {
            uint32_t phi[2][4], plo[2][4];
            #pragma unroll
            for (int r = 0; r < 2; r++)
                #pragma unroll
                for (int h2 = 0; h2 < 2; h2++) {
                    const float* pv = sc[r * 8 + kp * 2 + h2];
                    #pragma unroll
                    for (int p2 = 0; p2 < 2; p2++) {
                        float a = pv[2 * p2], b = pv[2 * p2 + 1];
                        uint32_t h = pack_bf16x2(a, b);
                        float ha = __int_as_float(h << 16);
                        float hb = __int_as_float(h & 0xffff0000u);
                        phi[r][h2 * 2 + p2] = h;
                        plo[r][h2 * 2 + p2] = pack_bf16x2(a - ha, b - hb);
                    }
                }
            #pragma unroll
            for (int qd = 0; qd < 4; qd++) {
                int vrow = nh * 64 + kp * 16 + ((lane >> 3) & 1) * 8 + (lane & 7);
                int vcol = qd * 16 + ((lane >> 4) & 1) * 8;
                uint32_t sb = swz((uint32_t)(vrow * 128 + vcol * 2));
                uint32_t vh[4], vl[4];
                ldsm4t(vh, cb + 32768 + sb);
                ldsm4t(vl, cb + 49152 + sb);
                #pragma unroll
                for (int r = 0; r < 2; r++) {
                    mma16816(oc[r][2 * qd],     phi[r], vh);
                    mma16816(oc[r][2 * qd],     phi[r], vl);
                    mma16816(oc[r][2 * qd],     plo[r], vh);
                    mma16816(oc[r][2 * qd + 1], phi[r], vh + 2);
                    mma16816(oc[r][2 * qd + 1], phi[r], vl + 2);
                    mma16816(oc[r][2 * qd + 1], plo[r], vh + 2);
                }
            }
        }

        if (i < 127) CP_WAIT0();
        __syncthreads();
    }

    // ---- cross-warp reduction: key-half partners (nh=0/1) combine ----
    float* ored = (float*)(smem + 32768);          // 4 x 32 x 64 fp32 = 32KB
    float* rsum = (float*)(smem + 65536);          // 2 x 128 fp32

    #pragma unroll
    for (int r = 0; r < 2; r++)
        #pragma unroll
        for (int h = 0; h < 2; h++) {
            float v = lsum[r][h];
            v += __shfl_xor_sync(0xffffffffu, v, 1);
            v += __shfl_xor_sync(0xffffffffu, v, 2);
            if (g == 0) rsum[nh * 128 + mi * 32 + r * 16 + h * 8 + hr] = v;
        }

    if (nh == 1) {
        float* dst = ored + mi * 2048;
        #pragma unroll
        for (int r = 0; r < 2; r++)
            #pragma unroll
            for (int qd = 0; qd < 4; qd++)
                #pragma unroll
                for (int hx = 0; hx < 2; hx++) {
                    int col = qd * 16 + hx * 8 + 2 * g;
                    int f = 2 * qd + hx;
                    *(float2*)(dst + (r * 16 + hr) * 64 + col) =
                        make_float2(oc[r][f][0], oc[r][f][1]);
                    *(float2*)(dst + (r * 16 + 8 + hr) * 64 + col) =
                        make_float2(oc[r][f][2], oc[r][f][3]);
                }
    }
    __syncthreads();

    if (nh == 0) {
        const float* src = ored + mi * 2048;
        #pragma unroll
        for (int r = 0; r < 2; r++) {
            int gr0 = mi * 32 + r * 16 + hr;
            int gr1 = gr0 + 8;
            float rl0 = 1.f / (rsum[gr0] + rsum[128 + gr0]);
            float rl1 = 1.f / (rsum[gr1] + rsum[128 + gr1]);
            #pragma unroll
            for (int qd = 0; qd < 4; qd++)
                #pragma unroll
                for (int hx = 0; hx < 2; hx++) {
                    int col = qd * 16 + hx * 8 + 2 * g;
                    int f = 2 * qd + hx;
                    float2 p0 = *(const float2*)(src + (r * 16 + hr) * 64 + col);
                    float2 p1 = *(const float2*)(src + (r * 16 + 8 + hr) * 64 + col);
                    split_store(OH, OL, (size_t)(q0 + gr0) * 64 + col,
                                (oc[r][f][0] + p0.x) * rl0, (oc[r][f][1] + p0.y) * rl0);
                    split_store(OH, OL, (size_t)(q0 + gr1) * 64 + col,
                                (oc[r][f][2] + p1.x) * rl1, (oc[r][f][3] + p1.y) * rl1);
                }
        }
    }
}

// ---------------------------------------------------------------------------
extern "C" void kernel_launch(void* const* d_in, const int* in_sizes, int n_in,
                              void* d_out, int out_size)
{
    (void)in_sizes; (void)n_in; (void)out_size;
    const float* x    = (const float*)d_in[0];   // [2048,1024]
    const float* Wq   = (const float*)d_in[1];   // [1024,512]
    const float* Wkv  = (const float*)d_in[2];   // [1024,1024]
    const float* Wout = (const float*)d_in[3];   // [512,1024]
    const float* bout = (const float*)d_in[4];   // [1024]
    float* out = (float*)d_out;                  // [2048,1024]

    __nv_bfloat16 *XH, *XL, *WaH, *WaL, *WoH, *WoL, *PH, *PL, *AH, *AL;
    cudaGetSymbolAddress((void**)&XH,  g_XH);   cudaGetSymbolAddress((void**)&XL,  g_XL);
    cudaGetSymbolAddress((void**)&WaH, g_WaH);  cudaGetSymbolAddress((void**)&WaL, g_WaL);
    cudaGetSymbolAddress((void**)&WoH, g_WoH);  cudaGetSymbolAddress((void**)&WoL, g_WoL);
    cudaGetSymbolAddress((void**)&PH,  g_QKVH); cudaGetSymbolAddress((void**)&PL,  g_QKVL);
    cudaGetSymbolAddress((void**)&AH,  g_AoH);  cudaGetSymbolAddress((void**)&AL,  g_AoL);

    prep_split<<<2048 * 1024 / 256, 256>>>(x,    XH,  XL);
    prep_split<<<512  * 1024 / 256, 256>>>(Wout, WoH, WoL);
    prep_pack <<<1024 * 1536 / 256, 256>>>(Wq, Wkv, WaH, WaL);

    cudaFuncSetAttribute(hgemm, cudaFuncAttributeMaxDynamicSharedMemorySize, 131072);
    cudaFuncSetAttribute(flashmma, cudaFuncAttributeMaxDynamicSharedMemorySize, 163840);

    // fused Q|K|V projection: [2048,1024] @ [1024,1536] -> segmented split-bf16
    hgemm<<<dim3(12, 16), 256, 131072>>>(XH, XL, 1024, WaH, WaL, 1536, 1024,
                                         nullptr, nullptr, 0, PH, PL, 512, SEG, 1);

    // flash attention -> split bf16 Ao
    flashmma<<<NROWS / 128, 256, 163840>>>(PH, PL, PH + SEG, PL + SEG,
                                           PH + 2 * SEG, PL + 2 * SEG, AH, AL);

    // out = Ao@Wout + bout (fp32)
    hgemm<<<dim3(8, 16), 256, 131072>>>(AH, AL, 512, WoH, WoL, 1024, 512,
                                        out, bout, 1024, nullptr, nullptr, 0, 0, 0);
}

// round 17
// speedup vs baseline: 1.0323x; 1.0323x over previous
#include <cuda_runtime.h>
#include <cuda_bf16.h>
#include <cstdint>

#define NROWS 16384
#define SEG   ((size_t)NROWS * 64)

// split bf16 buffers
static __device__ __nv_bfloat16 g_XH  [2048 * 1024];
static __device__ __nv_bfloat16 g_XL  [2048 * 1024];
static __device__ __nv_bfloat16 g_WaH [1024 * 1536];   // [Wq | Wkv] packed
static __device__ __nv_bfloat16 g_WaL [1024 * 1536];
static __device__ __nv_bfloat16 g_WoH [512 * 1024];
static __device__ __nv_bfloat16 g_WoL [512 * 1024];
static __device__ __nv_bfloat16 g_QKVH[3 * NROWS * 64];  // Q | K | V
static __device__ __nv_bfloat16 g_QKVL[3 * NROWS * 64];
static __device__ __nv_bfloat16 g_AoH [NROWS * 64];
static __device__ __nv_bfloat16 g_AoL [NROWS * 64];

// ---------------------------- helpers --------------------------------------
__device__ __forceinline__ uint32_t smem_u32(const void* p) {
    uint32_t a;
    asm("{ .reg .u64 t; cvta.to.shared.u64 t, %1; cvt.u32.u64 %0, t; }" : "=r"(a) : "l"(p));
    return a;
}
__device__ __forceinline__ uint32_t swz(uint32_t b) { return b ^ ((b >> 3) & 0x70); }

__device__ __forceinline__ void cpa16(uint32_t dst, const void* src) {
    asm volatile("cp.async.cg.shared.global [%0], [%1], 16;" :: "r"(dst), "l"(src) : "memory");
}
#define CP_COMMIT() asm volatile("cp.async.commit_group;" ::: "memory")
#define CP_WAIT0()  asm volatile("cp.async.wait_group 0;" ::: "memory")

__device__ __forceinline__ void ldsm4(uint32_t* r, uint32_t addr) {
    asm volatile("ldmatrix.sync.aligned.m8n8.x4.shared.b16 {%0,%1,%2,%3}, [%4];"
        : "=r"(r[0]), "=r"(r[1]), "=r"(r[2]), "=r"(r[3]) : "r"(addr));
}
__device__ __forceinline__ void ldsm4t(uint32_t* r, uint32_t addr) {
    asm volatile("ldmatrix.sync.aligned.m8n8.x4.trans.shared.b16 {%0,%1,%2,%3}, [%4];"
        : "=r"(r[0]), "=r"(r[1]), "=r"(r[2]), "=r"(r[3]) : "r"(addr));
}
__device__ __forceinline__ void mma16816(float* c, const uint32_t* a, const uint32_t* b) {
    asm volatile("mma.sync.aligned.m16n8k16.row.col.f32.bf16.bf16.f32 "
        "{%0,%1,%2,%3}, {%4,%5,%6,%7}, {%8,%9}, {%0,%1,%2,%3};"
        : "+f"(c[0]), "+f"(c[1]), "+f"(c[2]), "+f"(c[3])
        : "r"(a[0]), "r"(a[1]), "r"(a[2]), "r"(a[3]), "r"(b[0]), "r"(b[1]));
}
__device__ __forceinline__ uint32_t pack_bf16x2(float a, float b) {
    uint32_t h; asm("cvt.rn.bf16x2.f32 %0, %1, %2;" : "=r"(h) : "f"(b), "f"(a));
    return h;   // lo halfword = a, hi halfword = b
}
__device__ __forceinline__ void split_store(__nv_bfloat16* H, __nv_bfloat16* L,
                                            size_t off, float a, float b) {
    uint32_t h = pack_bf16x2(a, b);
    float ha = __int_as_float(h << 16);
    float hb = __int_as_float(h & 0xffff0000u);
    uint32_t l = pack_bf16x2(a - ha, b - hb);
    *(uint32_t*)(H + off) = h;
    *(uint32_t*)(L + off) = l;
}
// exp(0.125*s) via exp2 poly; |s| < ~24 here.
__device__ __forceinline__ float fexp8(float s) {
    float x = s * 0.18033688f;                 // 0.125 * log2(e)
    float t = x + 12582912.0f;
    int  ni = __float_as_int(t) - 0x4B400000;
    float r = x - (t - 12582912.0f);
    float p = 1.3333558e-3f;
    p = fmaf(p, r, 9.6181291e-3f);
    p = fmaf(p, r, 5.5504109e-2f);
    p = fmaf(p, r, 2.4022651e-1f);
    p = fmaf(p, r, 6.9314718e-1f);
    p = fmaf(p, r, 1.0f);
    return p * __int_as_float((ni + 127) << 23);
}

// ------------------------------- prep --------------------------------------
__global__ void prep_split(const float* __restrict__ X, __nv_bfloat16* __restrict__ H,
                           __nv_bfloat16* __restrict__ L)
{
    int i = blockIdx.x * 256 + threadIdx.x;
    float v = X[i];
    __nv_bfloat16 h = __float2bfloat16(v);
    H[i] = h;
    L[i] = __float2bfloat16(v - __bfloat162float(h));
}

__global__ void prep_pack(const float* __restrict__ Wq, const float* __restrict__ Wkv,
                          __nv_bfloat16* __restrict__ H, __nv_bfloat16* __restrict__ L)
{
    int i = blockIdx.x * 256 + threadIdx.x;     // over 1024*1536
    int k = i / 1536, c = i - k * 1536;
    float v = (c < 512) ? Wq[k * 512 + c] : Wkv[k * 1024 + (c - 512)];
    __nv_bfloat16 h = __float2bfloat16(v);
    H[i] = h;
    L[i] = __float2bfloat16(v - __bfloat162float(h));
}

// ---------------------------------------------------------------------------
// Split-bf16 HMMA GEMM (unchanged, proven).  C = A@B, 3-term hi/lo.
// ---------------------------------------------------------------------------
__global__ __launch_bounds__(256, 1)
void hgemm(const __nv_bfloat16* __restrict__ AH, const __nv_bfloat16* __restrict__ AL, int lda,
           const __nv_bfloat16* __restrict__ BH, const __nv_bfloat16* __restrict__ BL, int ldb,
           int Kdim,
           float* __restrict__ Cf, const float* __restrict__ bias, int ldc,
           __nv_bfloat16* __restrict__ CH, __nv_bfloat16* __restrict__ CL, int ldcs,
           size_t seg, int mode)
{
    extern __shared__ char smem[];
    const int tid = threadIdx.x, w = tid >> 5, lane = tid & 31;
    const int g = lane & 3, hr = lane >> 2;
    const uint32_t smb = smem_u32(smem);
    const int n0 = blockIdx.x * 128, m0 = blockIdx.y * 128;
    const int S = Kdim >> 6;

    auto load_stage = [&](int s, int b) {
        const uint32_t bb = smb + (uint32_t)b * 65536;
        const int k0 = s << 6;
        #pragma unroll
        for (int j = 0; j < 4; j++) {
            int f = tid + 256 * j;
            {   // A: 128 rows x 8 chunks
                int row = f >> 3, c = f & 7;
                uint32_t d = swz((uint32_t)(row * 128 + c * 16));
                const size_t so = (size_t)(m0 + row) * lda + k0 + c * 8;
                cpa16(bb + d,         AH + so);
                cpa16(bb + 16384 + d, AL + so);
            }
            {   // B: 64 k-rows x 16 chunks -> 2 panels
                int k = f >> 4, t = f & 15;
                uint32_t d = (uint32_t)((t >> 3) * 8192) + swz((uint32_t)(k * 128 + (t & 7) * 16));
                const size_t so = (size_t)(k0 + k) * ldb + n0 + t * 8;
                cpa16(bb + 32768 + d, BH + so);
                cpa16(bb + 49152 + d, BL + so);
            }
        }
        CP_COMMIT();
    };

    load_stage(0, 0);
    CP_WAIT0();
    __syncthreads();

    float acc[16][4];
    #pragma unroll
    for (int j = 0; j < 16; j++)
        #pragma unroll
        for (int e = 0; e < 4; e++) acc[j][e] = 0.f;

    const int arow = w * 16 + ((lane >> 3) & 1) * 8 + (lane & 7);
    const int acolh = ((lane >> 4) & 1) * 8;
    const int brow8 = ((lane >> 3) & 1) * 8 + (lane & 7);
    const int bcolh = ((lane >> 4) & 1) * 8;

    for (int i = 0; i < S; i++) {
        const uint32_t cb = smb + (uint32_t)(i & 1) * 65536;
        if (i + 1 < S) load_stage(i + 1, (i + 1) & 1);

        #pragma unroll
        for (int kk = 0; kk < 4; kk++) {
            uint32_t ah[4], al[4];
            uint32_t sa = swz((uint32_t)(arow * 128 + (kk * 16 + acolh) * 2));
            ldsm4(ah, cb + sa);
            ldsm4(al, cb + 16384 + sa);
            #pragma unroll
            for (int t = 0; t < 8; t++) {
                int ncol = ((t * 16) & 63) + bcolh;
                uint32_t sb = (uint32_t)((t >> 2) * 8192)
                            + swz((uint32_t)((kk * 16 + brow8) * 128 + ncol * 2));
                uint32_t bh[4], bl[4];
                ldsm4t(bh, cb + 32768 + sb);
                ldsm4t(bl, cb + 49152 + sb);
                mma16816(acc[2 * t],     ah, bh);
                mma16816(acc[2 * t],     ah, bl);
                mma16816(acc[2 * t],     al, bh);
                mma16816(acc[2 * t + 1], ah, bh + 2);
                mma16816(acc[2 * t + 1], ah, bl + 2);
                mma16816(acc[2 * t + 1], al, bh + 2);
            }
        }
        if (i + 1 < S) CP_WAIT0();
        __syncthreads();
    }

    const int r0 = m0 + w * 16 + hr;
    const int r1 = r0 + 8;
    if (mode == 0) {
        #pragma unroll
        for (int jo = 0; jo < 16; jo++) {
            int col = n0 + (jo >> 1) * 16 + (jo & 1) * 8 + 2 * g;
            float bx = bias ? bias[col] : 0.f, by = bias ? bias[col + 1] : 0.f;
            *(float2*)(Cf + (size_t)r0 * ldc + col) = make_float2(acc[jo][0] + bx, acc[jo][1] + by);
            *(float2*)(Cf + (size_t)r1 * ldc + col) = make_float2(acc[jo][2] + bx, acc[jo][3] + by);
        }
    } else {
        #pragma unroll
        for (int jo = 0; jo < 16; jo++) {
            int col = n0 + (jo >> 1) * 16 + (jo & 1) * 8 + 2 * g;
            size_t base = (size_t)(col >> 9) * seg + (size_t)(col & 511);
            split_store(CH, CL, base + (size_t)r0 * ldcs, acc[jo][0], acc[jo][1]);
            split_store(CH, CL, base + (size_t)r1 * ldcs, acc[jo][2], acc[jo][3]);
        }
    }
}

// ---------------------------------------------------------------------------
// HMMA flash attention, split-bf16 3-term, no online max.  OCCUPANCY BUILD:
// q-tile 64, key tile 64, grid 256, 80KB smem, <=128 regs -> 2 CTAs/SM
// (16 warps/SM) so one CTA's exp phase overlaps the other's mma phase.
// Warps: m16 (mi=w&3) x key-half n32 (nh=w>>2).  Q frags re-read from smem
// each tile (saves 32 regs).  2-way end reduction via smem (reuses KV buf).
// SMEM: QH 8K | QL 8K | 2 x { KH 8K | KL 8K | VH 8K | VL 8K }  = 80KB.
// ---------------------------------------------------------------------------
__global__ __launch_bounds__(256, 2)
void flashmma(const __nv_bfloat16* __restrict__ QH, const __nv_bfloat16* __restrict__ QL,
              const __nv_bfloat16* __restrict__ KH, const __nv_bfloat16* __restrict__ KL,
              const __nv_bfloat16* __restrict__ VH, const __nv_bfloat16* __restrict__ VL,
              __nv_bfloat16* __restrict__ OH, __nv_bfloat16* __restrict__ OL)
{
    extern __shared__ char smem[];
    const int tid = threadIdx.x, w = tid >> 5, lane = tid & 31;
    const int g = lane & 3, hr = lane >> 2;
    const int mi = w & 3, nh = w >> 2;
    const uint32_t smb = smem_u32(smem);
    const uint32_t QHs = smb, QLs = smb + 8192;
    const uint32_t BUF = smb + 16384;          // 2 x 32KB
    const int q0 = blockIdx.x * 64;

    // prologue: Q tile + K/V tile 0 via cp.async (512 chunks each array)
    #pragma unroll
    for (int j = 0; j < 2; j++) {
        int f = tid + 256 * j;                 // 0..511
        uint32_t d = swz((uint32_t)f * 16);
        cpa16(QHs + d, QH + (size_t)q0 * 64 + (size_t)f * 8);
        cpa16(QLs + d, QL + (size_t)q0 * 64 + (size_t)f * 8);
        cpa16(BUF +         d, KH + (size_t)f * 8);
        cpa16(BUF +  8192 + d, KL + (size_t)f * 8);
        cpa16(BUF + 16384 + d, VH + (size_t)f * 8);
        cpa16(BUF + 24576 + d, VL + (size_t)f * 8);
    }
    CP_COMMIT();
    CP_WAIT0();
    __syncthreads();

    const int arow  = mi * 16 + ((lane >> 3) & 1) * 8 + (lane & 7);
    const int acolh = ((lane >> 4) & 1) * 8;

    float oc[8][4];
    #pragma unroll
    for (int j = 0; j < 8; j++)
        #pragma unroll
        for (int e = 0; e < 4; e++) oc[j][e] = 0.f;
    float lsum0 = 0.f, lsum1 = 0.f;

    for (int i = 0; i < 256; i++) {
        const uint32_t cb = BUF + (uint32_t)(i & 1) * 32768;

        if (i < 255) {
            size_t base = (size_t)(i + 1) * 4096;
            uint32_t nb = BUF + (uint32_t)((i + 1) & 1) * 32768;
            #pragma unroll
            for (int j = 0; j < 2; j++) {
                int f = tid + 256 * j;
                uint32_t d = swz((uint32_t)f * 16);
                cpa16(nb +         d, KH + base + (size_t)f * 8);
                cpa16(nb +  8192 + d, KL + base + (size_t)f * 8);
                cpa16(nb + 16384 + d, VH + base + (size_t)f * 8);
                cpa16(nb + 24576 + d, VL + base + (size_t)f * 8);
            }
            CP_COMMIT();
        }

        // ---- S = Q K^T over this warp's key-half (m16 x n32) ----
        float sc[4][4];
        #pragma unroll
        for (int j = 0; j < 4; j++)
            #pragma unroll
            for (int e = 0; e < 4; e++) sc[j][e] = 0.f;

        #pragma unroll
        for (int ks = 0; ks < 4; ks++) {
            uint32_t ah[4], al[4];
            uint32_t sa = swz((uint32_t)(arow * 128 + (ks * 16 + acolh) * 2));
            ldsm4(ah, QHs + sa);
            ldsm4(al, QLs + sa);
            #pragma unroll
            for (int np = 0; np < 2; np++) {
                int krow = nh * 32 + np * 16 + ((lane >> 4) & 1) * 8 + (lane & 7);
                int kcol = ks * 16 + ((lane >> 3) & 1) * 8;
                uint32_t sb = swz((uint32_t)(krow * 128 + kcol * 2));
                uint32_t bh[4], bl[4];
                ldsm4(bh, cb + sb);
                ldsm4(bl, cb + 8192 + sb);
                float* s0 = sc[np * 2];
                float* s1 = sc[np * 2 + 1];
                mma16816(s0, ah, bh);
                mma16816(s0, ah, bl);
                mma16816(s0, al, bh);
                mma16816(s1, ah, bh + 2);
                mma16816(s1, ah, bl + 2);
                mma16816(s1, al, bh + 2);
            }
        }

        // ---- p = exp(s/8); partial row sums (c0,c1 -> row hr; c2,c3 -> hr+8) ----
        #pragma unroll
        for (int j = 0; j < 4; j++) {
            sc[j][0] = fexp8(sc[j][0]); sc[j][1] = fexp8(sc[j][1]);
            sc[j][2] = fexp8(sc[j][2]); sc[j][3] = fexp8(sc[j][3]);
            lsum0 += sc[j][0] + sc[j][1];
            lsum1 += sc[j][2] + sc[j][3];
        }

        // ---- O_partial += P V over this warp's k-half ----
        #pragma unroll
        for (int kp = 0; kp < 2; kp++) {
            uint32_t phi[4], plo[4];
            #pragma unroll
            for (int h2 = 0; h2 < 2; h2++) {
                const float* pv = sc[kp * 2 + h2];
                #pragma unroll
                for (int p2 = 0; p2 < 2; p2++) {
                    float a = pv[2 * p2], b = pv[2 * p2 + 1];
                    uint32_t h = pack_bf16x2(a, b);
                    float ha = __int_as_float(h << 16);
                    float hb = __int_as_float(h & 0xffff0000u);
                    phi[h2 * 2 + p2] = h;
                    plo[h2 * 2 + p2] = pack_bf16x2(a - ha, b - hb);
                }
            }
            int vrow = nh * 32 + kp * 16 + ((lane >> 3) & 1) * 8 + (lane & 7);
            #pragma unroll
            for (int qd = 0; qd < 4; qd++) {
                int vcol = qd * 16 + ((lane >> 4) & 1) * 8;
                uint32_t sb = swz((uint32_t)(vrow * 128 + vcol * 2));
                uint32_t vh[4], vl[4];
                ldsm4t(vh, cb + 16384 + sb);
                ldsm4t(vl, cb + 24576 + sb);
                mma16816(oc[2 * qd],     phi, vh);
                mma16816(oc[2 * qd],     phi, vl);
                mma16816(oc[2 * qd],     plo, vh);
                mma16816(oc[2 * qd + 1], phi, vh + 2);
                mma16816(oc[2 * qd + 1], phi, vl + 2);
                mma16816(oc[2 * qd + 1], plo, vh + 2);
            }
        }

        if (i < 255) CP_WAIT0();
        __syncthreads();
    }

    // ---- cross-warp reduction: key-half partners (nh=0/1) combine ----
    float* ored = (float*)(smem + 16384);          // 64 x 64 fp32 = 16KB
    float* rsum = (float*)(smem + 32768);          // 2 x 64 fp32

    {
        float v0 = lsum0, v1 = lsum1;
        v0 += __shfl_xor_sync(0xffffffffu, v0, 1);
        v0 += __shfl_xor_sync(0xffffffffu, v0, 2);
        v1 += __shfl_xor_sync(0xffffffffu, v1, 1);
        v1 += __shfl_xor_sync(0xffffffffu, v1, 2);
        if (g == 0) {
            rsum[nh * 64 + mi * 16 + hr]     = v0;
            rsum[nh * 64 + mi * 16 + 8 + hr] = v1;
        }
    }

    if (nh == 1) {
        #pragma unroll
        for (int qd = 0; qd < 4; qd++)
            #pragma unroll
            for (int hx = 0; hx < 2; hx++) {
                int col = qd * 16 + hx * 8 + 2 * g;
                int f = 2 * qd + hx;
                *(float2*)(ored + (mi * 16 + hr) * 64 + col) =
                    make_float2(oc[f][0], oc[f][1]);
                *(float2*)(ored + (mi * 16 + 8 + hr) * 64 + col) =
                    make_float2(oc[f][2], oc[f][3]);
            }
    }
    __syncthreads();

    if (nh == 0) {
        int gr0 = mi * 16 + hr;
        int gr1 = gr0 + 8;
        float rl0 = 1.f / (rsum[gr0] + rsum[64 + gr0]);
        float rl1 = 1.f / (rsum[gr1] + rsum[64 + gr1]);
        #pragma unroll
        for (int qd = 0; qd < 4; qd++)
            #pragma unroll
            for (int hx = 0; hx < 2; hx++) {
                int col = qd * 16 + hx * 8 + 2 * g;
                int f = 2 * qd + hx;
                float2 p0 = *(const float2*)(ored + gr0 * 64 + col);
                float2 p1 = *(const float2*)(ored + gr1 * 64 + col);
                split_store(OH, OL, (size_t)(q0 + gr0) * 64 + col,
                            (oc[f][0] + p0.x) * rl0, (oc[f][1] + p0.y) * rl0);
                split_store(OH, OL, (size_t)(q0 + gr1) * 64 + col,
                            (oc[f][2] + p1.x) * rl1, (oc[f][3] + p1.y) * rl1);
            }
    }
}

// ---------------------------------------------------------------------------
extern "C" void kernel_launch(void* const* d_in, const int* in_sizes, int n_in,
                              void* d_out, int out_size)
{
    (void)in_sizes; (void)n_in; (void)out_size;
    const float* x    = (const float*)d_in[0];   // [2048,1024]
    const float* Wq   = (const float*)d_in[1];   // [1024,512]
    const float* Wkv  = (const float*)d_in[2];   // [1024,1024]
    const float* Wout = (const float*)d_in[3];   // [512,1024]
    const float* bout = (const float*)d_in[4];   // [1024]
    float* out = (float*)d_out;                  // [2048,1024]

    __nv_bfloat16 *XH, *XL, *WaH, *WaL, *WoH, *WoL, *PH, *PL, *AH, *AL;
    cudaGetSymbolAddress((void**)&XH,  g_XH);   cudaGetSymbolAddress((void**)&XL,  g_XL);
    cudaGetSymbolAddress((void**)&WaH, g_WaH);  cudaGetSymbolAddress((void**)&WaL, g_WaL);
    cudaGetSymbolAddress((void**)&WoH, g_WoH);  cudaGetSymbolAddress((void**)&WoL, g_WoL);
    cudaGetSymbolAddress((void**)&PH,  g_QKVH); cudaGetSymbolAddress((void**)&PL,  g_QKVL);
    cudaGetSymbolAddress((void**)&AH,  g_AoH);  cudaGetSymbolAddress((void**)&AL,  g_AoL);

    prep_split<<<2048 * 1024 / 256, 256>>>(x,    XH,  XL);
    prep_split<<<512  * 1024 / 256, 256>>>(Wout, WoH, WoL);
    prep_pack <<<1024 * 1536 / 256, 256>>>(Wq, Wkv, WaH, WaL);

    cudaFuncSetAttribute(hgemm, cudaFuncAttributeMaxDynamicSharedMemorySize, 131072);
    cudaFuncSetAttribute(flashmma, cudaFuncAttributeMaxDynamicSharedMemorySize, 81920);

    // fused Q|K|V projection: [2048,1024] @ [1024,1536] -> segmented split-bf16
    hgemm<<<dim3(12, 16), 256, 131072>>>(XH, XL, 1024, WaH, WaL, 1536, 1024,
                                         nullptr, nullptr, 0, PH, PL, 512, SEG, 1);

    // flash attention -> split bf16 Ao   (grid 256, 2 CTAs/SM)
    flashmma<<<NROWS / 64, 256, 81920>>>(PH, PL, PH + SEG, PL + SEG,
                                         PH + 2 * SEG, PL + 2 * SEG, AH, AL);

    // out = Ao@Wout + bout (fp32)
    hgemm<<<dim3(8, 16), 256, 131072>>>(AH, AL, 512, WoH, WoL, 1024, 512,
                                        out, bout, 1024, nullptr, nullptr, 0, 0, 0);
}